// round 11
// baseline (speedup 1.0000x reference)
#include <cuda_runtime.h>
#include <math_constants.h>
#include <cstdint>

#define BATCH 8192
#define DIM   512
#define NCLS  512
#define T_INV 14.2857142857142857f  // 1/0.07

#define NSTRIP 64
#define NTILE  (NSTRIP * (NSTRIP + 1) / 2)   // 2080 upper-tri tiles
#define NSLOT  64
#define PSTRIDE 16                 // 8 values + 8 indices per (row, slot)

#define MT     128
#define NT     128
#define KCB    128                 // K-bytes per chunk (int8)
#define NCHUNK (DIM / KCB)         // 4

#define PITCHB 144                 // bytes per SMEM row (conflict-free ldsm)
#define AB_BYTES (MT * PITCHB)             // 18432 per operand
#define STAGE_BYTES  (2 * AB_BYTES)        // 36864
#define CPITCH 132
#define SMEM_BYTES   (128 * CPITCH * 4 + 128 * 16 * 4)   // 75776 (C tile + pair xchg)
#define MAXM   256

// ---------------- static scratch ----------------
__device__ float  g_f[BATCH * DIM];        // normalized fp32 features
__device__ int8_t g_q[BATCH * DIM];        // quantized features
__device__ float  g_sinv[BATCH];           // per-row dequant scale
__device__ int    g_idx[BATCH];
__device__ unsigned g_Gkey;
__device__ float g_part[(size_t)BATCH * NSLOT * PSTRIDE];
__device__ int   g_cand[BATCH * 8];
__device__ int   g_ccount[NCLS], g_coff[NCLS];
__device__ int   g_bmem[BATCH];
__device__ float g_D1[BATCH], g_H[BATCH], g_B[BATCH];

// ---------------- helpers ----------------
__device__ __forceinline__ uint32_t smem_u32(const void* p) {
    uint32_t a;
    asm("{ .reg .u64 t; cvta.to.shared.u64 t, %1; cvt.u32.u64 %0, t; }" : "=r"(a) : "l"(p));
    return a;
}
__device__ __forceinline__ void cpa16(uint32_t dst, const void* src) {
    asm volatile("cp.async.cg.shared.global [%0], [%1], 16;" :: "r"(dst), "l"(src));
}
#define CP_COMMIT() asm volatile("cp.async.commit_group;" ::: "memory")
#define CP_WAIT1()  asm volatile("cp.async.wait_group 1;" ::: "memory")
#define CP_WAIT0()  asm volatile("cp.async.wait_group 0;" ::: "memory")

__device__ __forceinline__ void ldsm_x4(uint32_t* r, uint32_t addr) {
    asm volatile("ldmatrix.sync.aligned.m8n8.x4.shared.b16 {%0,%1,%2,%3}, [%4];"
                 : "=r"(r[0]), "=r"(r[1]), "=r"(r[2]), "=r"(r[3]) : "r"(addr));
}
__device__ __forceinline__ void mma32i(int* c, const uint32_t* a, uint32_t b0, uint32_t b1) {
    asm volatile(
        "mma.sync.aligned.m16n8k32.row.col.s32.s8.s8.s32 "
        "{%0,%1,%2,%3}, {%4,%5,%6,%7}, {%8,%9}, {%0,%1,%2,%3};"
        : "+r"(c[0]), "+r"(c[1]), "+r"(c[2]), "+r"(c[3])
        : "r"(a[0]), "r"(a[1]), "r"(a[2]), "r"(a[3]), "r"(b0), "r"(b1));
}

__device__ __forceinline__ unsigned fkey(float f) {
    unsigned u = __float_as_uint(f);
    return (u & 0x80000000u) ? ~u : (u | 0x80000000u);
}
__device__ __forceinline__ float funkey(unsigned k) {
    unsigned u = (k & 0x80000000u) ? (k & 0x7FFFFFFFu) : ~k;
    return __uint_as_float(u);
}
__device__ __forceinline__ void top5_ins(float v, float& t0, float& t1, float& t2,
                                         float& t3, float& t4) {
    if (v > t4) {
        float w = v, tmp;
        if (w > t0) { tmp = t0; t0 = w; w = tmp; }
        if (w > t1) { tmp = t1; t1 = w; w = tmp; }
        if (w > t2) { tmp = t2; t2 = w; w = tmp; }
        if (w > t3) { tmp = t3; t3 = w; w = tmp; }
        t4 = w;
    }
}
__device__ __forceinline__ void top8_ins(float val, int idx, float (&v)[8], int (&id)[8]) {
    if (val > v[7]) {
        float cv = val; int ci = idx;
        #pragma unroll
        for (int k = 0; k < 8; k++) {
            if (cv > v[k]) {
                float tv = v[k]; int ti = id[k];
                v[k] = cv; id[k] = ci; cv = tv; ci = ti;
            }
        }
    }
}
__device__ __forceinline__ int q8(float v) {
    int q = (int)rintf(v);
    q = q > 127 ? 127 : (q < -127 ? -127 : q);
    return q & 0xff;
}

// ---------------------------------------------------------------------------
// Kernel 0: index canonicalization (int32 vs int64) + G reset
// ---------------------------------------------------------------------------
__global__ void prep_idx_kernel(const int* __restrict__ raw) {
    __shared__ int sh[256];
    int tid = threadIdx.x;
    int acc = 0;
    for (int i = tid; i < BATCH / 2; i += 256) acc |= raw[2 * i + 1];
    sh[tid] = acc;
    __syncthreads();
    for (int s = 128; s; s >>= 1) { if (tid < s) sh[tid] |= sh[tid + s]; __syncthreads(); }
    bool is64 = (sh[0] == 0);
    for (int i = tid; i < BATCH; i += 256) g_idx[i] = is64 ? raw[2 * i] : raw[i];
    if (tid == 0) g_Gkey = 0u;
}

// ---------------------------------------------------------------------------
// Kernel 1: L2 normalize -> fp32 g_f + int8 g_q (scale = 127/max|f|)
// ---------------------------------------------------------------------------
__global__ void normalize_kernel(const float* __restrict__ x) {
    int row = blockIdx.x;
    int t = threadIdx.x;
    float4 v = ((const float4*)(x + row * DIM))[t];
    float ss = v.x * v.x + v.y * v.y + v.z * v.z + v.w * v.w;
    float mx = fmaxf(fmaxf(fabsf(v.x), fabsf(v.y)), fmaxf(fabsf(v.z), fabsf(v.w)));
    #pragma unroll
    for (int o = 16; o; o >>= 1) {
        ss += __shfl_xor_sync(0xffffffffu, ss, o);
        mx = fmaxf(mx, __shfl_xor_sync(0xffffffffu, mx, o));
    }
    __shared__ float ws[4], wm[4];
    if ((t & 31) == 0) { ws[t >> 5] = ss; wm[t >> 5] = mx; }
    __syncthreads();
    float inv = 1.0f / fmaxf(sqrtf(ws[0] + ws[1] + ws[2] + ws[3]), 1e-12f);
    float fmx = fmaxf(fmaxf(wm[0], wm[1]), fmaxf(wm[2], wm[3])) * inv;
    fmx = fmaxf(fmx, 1e-20f);
    float s = 127.0f / fmx;
    if (t == 0) g_sinv[row] = fmx * (1.0f / 127.0f);
    float4 f = make_float4(v.x * inv, v.y * inv, v.z * inv, v.w * inv);
    ((float4*)(g_f + (size_t)row * DIM))[t] = f;
    uint32_t w = (uint32_t)q8(f.x * s) | ((uint32_t)q8(f.y * s) << 8)
               | ((uint32_t)q8(f.z * s) << 16) | ((uint32_t)q8(f.w * s) << 24);
    ((uint32_t*)(g_q + (size_t)row * DIM))[t] = w;
}

// ---------------------------------------------------------------------------
// Kernels 1b/1c/1d: deterministic class buckets (count, prefix, fill)
// ---------------------------------------------------------------------------
__global__ void class_count_kernel() {
    int c = blockIdx.x, lane = threadIdx.x;
    int cnt = 0;
    for (int b = lane; b < BATCH; b += 32) cnt += (g_idx[b] == c);
    #pragma unroll
    for (int o = 16; o; o >>= 1) cnt += __shfl_xor_sync(0xffffffffu, cnt, o);
    if (lane == 0) g_ccount[c] = cnt;
}
__global__ void class_prefix_kernel() {
    __shared__ int sh[NCLS];
    int t = threadIdx.x;
    int mine = g_ccount[t];
    sh[t] = mine;
    __syncthreads();
    for (int o = 1; o < NCLS; o <<= 1) {
        int u = (t >= o) ? sh[t - o] : 0;
        __syncthreads();
        sh[t] += u;
        __syncthreads();
    }
    g_coff[t] = sh[t] - mine;   // exclusive prefix
}
__global__ void class_fill_kernel() {
    int c = blockIdx.x, lane = threadIdx.x;
    int off = g_coff[c];
    int cnt = 0;
    for (int base = 0; base < BATCH; base += 32) {
        int j = base + lane;
        bool m = (g_idx[j] == c);
        unsigned mask = __ballot_sync(0xffffffffu, m);
        if (m) g_bmem[off + cnt + __popc(mask & ((1u << lane) - 1))] = j;
        cnt += __popc(mask);
    }
}

// ---------------------------------------------------------------------------
// Kernel 2: symmetric-triangle int8 MMA GEMM + dual top-8 candidate scans
// ---------------------------------------------------------------------------
__device__ __forceinline__ void prefetch_chunk(uint32_t s_base, int st, int row0,
                                               int col0, int kb, int tid) {
    const uint32_t stf = s_base + st * STAGE_BYTES;
    #pragma unroll
    for (int i = tid; i < MT * 8; i += 256) {
        int r = i >> 3, sg = i & 7;
        cpa16(stf + r * PITCHB + sg * 16, g_q + (size_t)(row0 + r) * DIM + kb + sg * 16);
    }
    #pragma unroll
    for (int i = tid; i < NT * 8; i += 256) {
        int r = i >> 3, sg = i & 7;
        cpa16(stf + AB_BYTES + r * PITCHB + sg * 16,
              g_q + (size_t)(col0 + r) * DIM + kb + sg * 16);
    }
    CP_COMMIT();
}

__global__ __launch_bounds__(256, 2)
void sim_kernel() {
    extern __shared__ float smem[];
    const uint32_t s_base = smem_u32(smem);
    const int tid  = threadIdx.x;
    const int lane = tid & 31, warp = tid >> 5;

    const int b = blockIdx.x;
    int J = (int)((sqrtf(8.0f * b + 1.0f) - 1.0f) * 0.5f);
    while ((J + 1) * (J + 2) / 2 <= b) ++J;
    while (J * (J + 1) / 2 > b) --J;
    const int I = b - J * (J + 1) / 2;
    const int row0 = I * MT;
    const int col0 = J * NT;

    const int wm = warp >> 1, wn = warp & 1;
    const int qg = lane >> 2, qt = lane & 3;

    uint32_t aoff[2], boff[4];
    {
        const int l7 = lane & 7, l8 = (lane >> 3) & 1, l16 = (lane >> 4) & 1;
        #pragma unroll
        for (int i = 0; i < 2; i++) {
            int rowA = wm * 32 + i * 16 + l8 * 8 + l7;
            aoff[i] = (uint32_t)(rowA * PITCHB + l16 * 16);
        }
        #pragma unroll
        for (int jp = 0; jp < 4; jp++) {
            int nB = wn * 64 + jp * 16 + l16 * 8 + l7;
            boff[jp] = (uint32_t)(AB_BYTES + nB * PITCHB + l8 * 16);
        }
    }

    int acc[2][8][4];
    #pragma unroll
    for (int i = 0; i < 2; i++)
        #pragma unroll
        for (int j = 0; j < 8; j++)
            #pragma unroll
            for (int q = 0; q < 4; q++) acc[i][j][q] = 0;

    prefetch_chunk(s_base, 0, row0, col0, 0, tid);
    prefetch_chunk(s_base, 1, row0, col0, KCB, tid);

    for (int c = 0; c < NCHUNK; c++) {
        const int st = c & 1;
        if (c >= NCHUNK - 2) { CP_WAIT0(); } else { CP_WAIT1(); }
        __syncthreads();
        const uint32_t stb = s_base + st * STAGE_BYTES;
        #pragma unroll
        for (int ks = 0; ks < 4; ks++) {
            const uint32_t ko = ks * 32;
            uint32_t a0[4], a1[4], bb[4][4];
            ldsm_x4(a0, stb + aoff[0] + ko);
            ldsm_x4(a1, stb + aoff[1] + ko);
            #pragma unroll
            for (int jp = 0; jp < 4; jp++) ldsm_x4(bb[jp], stb + boff[jp] + ko);
            #pragma unroll
            for (int jp = 0; jp < 4; jp++) {
                mma32i(acc[0][2 * jp],     a0, bb[jp][0], bb[jp][1]);
                mma32i(acc[1][2 * jp],     a1, bb[jp][0], bb[jp][1]);
                mma32i(acc[0][2 * jp + 1], a0, bb[jp][2], bb[jp][3]);
                mma32i(acc[1][2 * jp + 1], a1, bb[jp][2], bb[jp][3]);
            }
        }
        __syncthreads();
        if (c + 2 < NCHUNK)
            prefetch_chunk(s_base, st, row0, col0, (c + 2) * KCB, tid);
    }

    // dequant scales
    float ira[2][2], irb[8][2];
    #pragma unroll
    for (int i = 0; i < 2; i++) {
        ira[i][0] = g_sinv[row0 + wm * 32 + i * 16 + qg];
        ira[i][1] = g_sinv[row0 + wm * 32 + i * 16 + qg + 8];
    }
    #pragma unroll
    for (int j = 0; j < 8; j++) {
        irb[j][0] = g_sinv[col0 + wn * 64 + j * 8 + 2 * qt];
        irb[j][1] = g_sinv[col0 + wn * 64 + j * 8 + 2 * qt + 1];
    }

    float* Cs = smem;
    float* Ps = smem + 128 * CPITCH;    // 128 x 16 pair-exchange floats
    #pragma unroll
    for (int i = 0; i < 2; i++) {
        #pragma unroll
        for (int j = 0; j < 8; j++) {
            int r = wm * 32 + i * 16 + qg;
            int cc = wn * 64 + j * 8 + 2 * qt;
            Cs[r * CPITCH + cc]           = (float)acc[i][j][0] * ira[i][0] * irb[j][0];
            Cs[r * CPITCH + cc + 1]       = (float)acc[i][j][1] * ira[i][0] * irb[j][1];
            Cs[(r + 8) * CPITCH + cc]     = (float)acc[i][j][2] * ira[i][1] * irb[j][0];
            Cs[(r + 8) * CPITCH + cc + 1] = (float)acc[i][j][3] * ira[i][1] * irb[j][1];
        }
    }
    __syncthreads();

    const int sidx = tid & 127, shalf = tid >> 7;

    // ---- row scan: top-8 (value,index) for strip I rows over strip J cols ----
    {
        const int myrow = row0 + sidx;
        const float* crow = Cs + sidx * CPITCH + shalf * 64;
        const int colbase = col0 + shalf * 64;
        float v[8]; int id[8];
        #pragma unroll
        for (int k = 0; k < 8; k++) { v[k] = -CUDART_INF_F; id[k] = 0; }
        for (int cc = 0; cc < 64; cc++) {
            int gcol = colbase + cc;
            if (gcol == myrow) continue;
            top8_ins(crow[cc], gcol, v, id);
        }
        if (shalf) {
            float* pp = Ps + sidx * 16;
            #pragma unroll
            for (int k = 0; k < 8; k++) { pp[k] = v[k]; pp[8 + k] = __int_as_float(id[k]); }
        }
        __syncthreads();
        if (!shalf) {
            const float* pp = Ps + sidx * 16;
            #pragma unroll
            for (int k = 0; k < 8; k++) top8_ins(pp[k], __float_as_int(pp[8 + k]), v, id);
            float* gp = g_part + ((size_t)myrow * NSLOT + J) * PSTRIDE;
            #pragma unroll
            for (int k = 0; k < 8; k++) { gp[k] = v[k]; gp[8 + k] = __int_as_float(id[k]); }
        }
    }

    if (I == J) return;

    __syncthreads();

    // ---- col scan: top-8 for strip J rows over strip I cols ----
    {
        const int myrow = col0 + sidx;
        const int rbase = shalf * 64;
        float v[8]; int id[8];
        #pragma unroll
        for (int k = 0; k < 8; k++) { v[k] = -CUDART_INF_F; id[k] = 0; }
        for (int rr = 0; rr < 64; rr++)
            top8_ins(Cs[(rbase + rr) * CPITCH + sidx], row0 + rbase + rr, v, id);
        if (shalf) {
            float* pp = Ps + sidx * 16;
            #pragma unroll
            for (int k = 0; k < 8; k++) { pp[k] = v[k]; pp[8 + k] = __int_as_float(id[k]); }
        }
        __syncthreads();
        if (!shalf) {
            const float* pp = Ps + sidx * 16;
            #pragma unroll
            for (int k = 0; k < 8; k++) top8_ins(pp[k], __float_as_int(pp[8 + k]), v, id);
            float* gp = g_part + ((size_t)myrow * NSLOT + I) * PSTRIDE;
            #pragma unroll
            for (int k = 0; k < 8; k++) { gp[k] = v[k]; gp[8 + k] = __int_as_float(id[k]); }
        }
    }
}

// ---------------------------------------------------------------------------
// Kernel 3: merge 64 slots' top-8 -> 8 candidate indices per row
// ---------------------------------------------------------------------------
__global__ void merge_kernel() {
    const int tid = threadIdx.x;
    const int lane = tid & 31;
    const int sub = lane & 7;
    const int r = blockIdx.x * 32 + (tid >> 3);

    float v[8]; int id[8];
    #pragma unroll
    for (int k = 0; k < 8; k++) { v[k] = -CUDART_INF_F; id[k] = 0; }
    #pragma unroll
    for (int q = 0; q < 8; q++) {
        int s = sub + q * 8;
        const float4* gp = (const float4*)(g_part + ((size_t)r * NSLOT + s) * PSTRIDE);
        float4 a = gp[0], bq = gp[1], c = gp[2], d = gp[3];
        top8_ins(a.x, __float_as_int(c.x), v, id);
        top8_ins(a.y, __float_as_int(c.y), v, id);
        top8_ins(a.z, __float_as_int(c.z), v, id);
        top8_ins(a.w, __float_as_int(c.w), v, id);
        top8_ins(bq.x, __float_as_int(d.x), v, id);
        top8_ins(bq.y, __float_as_int(d.y), v, id);
        top8_ins(bq.z, __float_as_int(d.z), v, id);
        top8_ins(bq.w, __float_as_int(d.w), v, id);
    }
    #pragma unroll
    for (int o = 1; o < 8; o <<= 1) {
        float mv[8]; int mi[8];
        #pragma unroll
        for (int k = 0; k < 8; k++) {
            mv[k] = __shfl_xor_sync(0xffffffffu, v[k], o);
            mi[k] = __shfl_xor_sync(0xffffffffu, id[k], o);
        }
        #pragma unroll
        for (int k = 0; k < 8; k++) top8_ins(mv[k], mi[k], v, id);
    }
    if (sub == 0) {
        #pragma unroll
        for (int k = 0; k < 8; k++) g_cand[r * 8 + k] = id[k];
    }
}

// ---------------------------------------------------------------------------
// Kernel 4: exact refine — fp32 dots for 8 candidates + class positives
// ---------------------------------------------------------------------------
__global__ void refine_kernel() {
    __shared__ float fr[DIM];
    __shared__ int mlist[MAXM];
    __shared__ int clist[8];
    __shared__ float dres[8 + MAXM];
    const int r = blockIdx.x, tid = threadIdx.x;
    const int lane = tid & 31, w = tid >> 5;

    ((float4*)fr)[tid] = ((const float4*)(g_f + (size_t)r * DIM))[tid];
    const int c = g_idx[r];
    const int off = g_coff[c];
    int cnt = g_ccount[c];
    if (cnt > MAXM) cnt = MAXM;
    for (int m = tid; m < cnt; m += 128) mlist[m] = g_bmem[off + m];
    if (tid < 8) clist[tid] = g_cand[r * 8 + tid];
    __syncthreads();

    const int ntask = 8 + cnt;
    for (int t = w; t < ntask; t += 4) {
        int j = (t < 8) ? clist[t] : mlist[t - 8];
        const float4* fb = (const float4*)(g_f + (size_t)j * DIM);
        const float4* fa = (const float4*)fr;
        float s = 0.f;
        #pragma unroll
        for (int q = 0; q < 4; q++) {
            float4 a = fa[lane + q * 32];
            float4 bq = fb[lane + q * 32];
            s += a.x * bq.x + a.y * bq.y + a.z * bq.z + a.w * bq.w;
        }
        #pragma unroll
        for (int o = 16; o; o >>= 1) s += __shfl_xor_sync(0xffffffffu, s, o);
        if (lane == 0) dres[t] = s;
    }
    __syncthreads();

    if (tid == 0) {
        float t0 = -CUDART_INF_F, t1 = -CUDART_INF_F, t2 = -CUDART_INF_F,
              t3 = -CUDART_INF_F, t4 = -CUDART_INF_F;
        #pragma unroll
        for (int k = 0; k < 8; k++) top5_ins(dres[k], t0, t1, t2, t3, t4);
        float S = 0.f, P = 0.f, rm = -CUDART_INF_F;
        int n = 0;
        for (int m = 0; m < cnt; m++) {
            if (mlist[m] == r) continue;
            float vv = dres[8 + m];
            S += vv; rm = fmaxf(rm, vv); P += __expf(vv * T_INV); n++;
        }
        g_D1[r] = n ? __expf(-rm * T_INV) * P : 0.f;
        float H = __expf(t0 * T_INV) + __expf(t1 * T_INV) + __expf(t2 * T_INV) +
                  __expf(t3 * T_INV) + __expf(t4 * T_INV);
        g_H[r] = n ? H : -1.f;
        g_B[r] = n ? (S * T_INV) / (float)n : 0.f;
        atomicMax(&g_Gkey, fkey(t0));
    }
}

// ---------------------------------------------------------------------------
// Kernel 5: final loss
// ---------------------------------------------------------------------------
__global__ void finalize_kernel(float* __restrict__ out) {
    __shared__ float sh[1024];
    int tid = threadIdx.x;
    float G = funkey(g_Gkey) * T_INV;
    float eG = __expf(-G);
    float sum = 0.f;
    for (int r = tid; r < BATCH; r += 1024) {
        float H = g_H[r];
        if (H >= 0.f)
            sum += __logf(g_D1[r] + eG * H) - g_B[r];
    }
    sh[tid] = sum;
    __syncthreads();
    for (int s = 512; s; s >>= 1) {
        if (tid < s) sh[tid] += sh[tid + s];
        __syncthreads();
    }
    if (tid == 0) out[0] = sh[0] / (float)BATCH;
}

// ---------------------------------------------------------------------------
extern "C" void kernel_launch(void* const* d_in, const int* in_sizes, int n_in,
                              void* d_out, int out_size) {
    const float* x   = (const float*)d_in[0];
    const int*   idx = (const int*)d_in[1];
    float*       out = (float*)d_out;

    cudaFuncSetAttribute(sim_kernel, cudaFuncAttributeMaxDynamicSharedMemorySize,
                         SMEM_BYTES);

    prep_idx_kernel<<<1, 256>>>(idx);
    normalize_kernel<<<BATCH, 128>>>(x);
    class_count_kernel<<<NCLS, 32>>>();
    class_prefix_kernel<<<1, NCLS>>>();
    class_fill_kernel<<<NCLS, 32>>>();
    sim_kernel<<<NTILE, 256, SMEM_BYTES>>>();
    merge_kernel<<<BATCH / 32, 256>>>();
    refine_kernel<<<BATCH, 128>>>();
    finalize_kernel<<<1, 1024>>>(out);
}

// round 12
// speedup vs baseline: 2.1103x; 2.1103x over previous
#include <cuda_runtime.h>
#include <cuda_bf16.h>
#include <math_constants.h>
#include <cstdint>

#define BATCH 8192
#define DIM   512
#define T_INV 14.2857142857142857f  // 1/0.07

#define NSTRIP 64                  // 64 strips of 128 rows
#define NTILE  (NSTRIP * (NSTRIP + 1) / 2)   // 2080 upper-tri tiles
#define NSLOT  64
#define PSTRIDE 12                 // floats per partial record (9 used, f4-aligned)

#define MT     128
#define NT     128
#define KC     64                  // bf16 halves per chunk
#define NCHUNK (DIM / KC)          // 8

#define PITCHH 72                  // halves per SMEM row (144B; conflict-free frags)
#define AB_HALVES (MT * PITCHH)            // 9216 halves per operand
#define STAGE_HALVES (2 * AB_HALVES)
#define STAGE_BYTES  (STAGE_HALVES * 2)    // 36864
#define CPITCH 132
#define IDX_OFF (2 * STAGE_BYTES)          // idx arrays live past the stages
#define SMEM_BYTES (IDX_OFF + 1024)        // + idxI[128], idxJ[128]

// ---------------- static scratch ----------------
__device__ __nv_bfloat16 g_fb[BATCH * DIM];
__device__ int   g_idx[BATCH];
__device__ unsigned g_Gkey;
__device__ float g_part[(size_t)BATCH * NSLOT * PSTRIDE];
__device__ float g_D1[BATCH], g_H[BATCH], g_B[BATCH];

// ---------------- helpers ----------------
__device__ __forceinline__ uint32_t smem_u32(const void* p) {
    uint32_t a;
    asm("{ .reg .u64 t; cvta.to.shared.u64 t, %1; cvt.u32.u64 %0, t; }" : "=r"(a) : "l"(p));
    return a;
}
__device__ __forceinline__ void cpa16(uint32_t dst, const void* src) {
    asm volatile("cp.async.cg.shared.global [%0], [%1], 16;" :: "r"(dst), "l"(src));
}
#define CP_COMMIT() asm volatile("cp.async.commit_group;" ::: "memory")
#define CP_WAIT1()  asm volatile("cp.async.wait_group 1;" ::: "memory")
#define CP_WAIT0()  asm volatile("cp.async.wait_group 0;" ::: "memory")

__device__ __forceinline__ void ldsm_x4(uint32_t* r, uint32_t addr) {
    asm volatile("ldmatrix.sync.aligned.m8n8.x4.shared.b16 {%0,%1,%2,%3}, [%4];"
                 : "=r"(r[0]), "=r"(r[1]), "=r"(r[2]), "=r"(r[3]) : "r"(addr));
}
__device__ __forceinline__ void mma16(float* c, const uint32_t* a, uint32_t b0, uint32_t b1) {
    asm volatile(
        "mma.sync.aligned.m16n8k16.row.col.f32.bf16.bf16.f32 "
        "{%0,%1,%2,%3}, {%4,%5,%6,%7}, {%8,%9}, {%0,%1,%2,%3};"
        : "+f"(c[0]), "+f"(c[1]), "+f"(c[2]), "+f"(c[3])
        : "r"(a[0]), "r"(a[1]), "r"(a[2]), "r"(a[3]), "r"(b0), "r"(b1));
}

__device__ __forceinline__ unsigned fkey(float f) {
    unsigned u = __float_as_uint(f);
    return (u & 0x80000000u) ? ~u : (u | 0x80000000u);
}
__device__ __forceinline__ float funkey(unsigned k) {
    unsigned u = (k & 0x80000000u) ? (k & 0x7FFFFFFFu) : ~k;
    return __uint_as_float(u);
}
__device__ __forceinline__ void top5_ins(float v, float& t0, float& t1, float& t2,
                                         float& t3, float& t4) {
    if (v > t4) {
        float w = v, tmp;
        if (w > t0) { tmp = t0; t0 = w; w = tmp; }
        if (w > t1) { tmp = t1; t1 = w; w = tmp; }
        if (w > t2) { tmp = t2; t2 = w; w = tmp; }
        if (w > t3) { tmp = t3; t3 = w; w = tmp; }
        t4 = w;
    }
}

// scan state bundle
struct ScanAcc {
    float S, P, n, rm;
    float t0, t1, t2, t3, t4;
    __device__ __forceinline__ void init() {
        S = P = n = 0.f;
        rm = t0 = t1 = t2 = t3 = t4 = -CUDART_INF_F;
    }
    __device__ __forceinline__ void hard(float v) { top5_ins(v, t0, t1, t2, t3, t4); }
    __device__ __forceinline__ void pos(float v) {
        n += 1.0f; S += v; rm = fmaxf(rm, v); P += __expf(v * T_INV);
    }
};

// ---------------------------------------------------------------------------
// Kernel 0: dtype-agnostic index canonicalization (int32 vs int64) + G reset
// ---------------------------------------------------------------------------
__global__ void prep_idx_kernel(const int* __restrict__ raw) {
    __shared__ int sh[256];
    int tid = threadIdx.x;
    int acc = 0;
    for (int i = tid; i < BATCH / 2; i += 256) acc |= raw[2 * i + 1];
    sh[tid] = acc;
    __syncthreads();
    for (int s = 128; s; s >>= 1) { if (tid < s) sh[tid] |= sh[tid + s]; __syncthreads(); }
    bool is64 = (sh[0] == 0);
    for (int i = tid; i < BATCH; i += 256) g_idx[i] = is64 ? raw[2 * i] : raw[i];
    if (tid == 0) g_Gkey = 0u;
}

// ---------------------------------------------------------------------------
// Kernel 1: L2 normalize + round to bf16 (rn)
// ---------------------------------------------------------------------------
__global__ void normalize_kernel(const float* __restrict__ x) {
    int row = blockIdx.x;
    int t = threadIdx.x;
    float4 v = ((const float4*)(x + row * DIM))[t];
    float ss = v.x * v.x + v.y * v.y + v.z * v.z + v.w * v.w;
    #pragma unroll
    for (int o = 16; o; o >>= 1) ss += __shfl_xor_sync(0xffffffffu, ss, o);
    __shared__ float ws[4];
    if ((t & 31) == 0) ws[t >> 5] = ss;
    __syncthreads();
    float inv = 1.0f / fmaxf(sqrtf(ws[0] + ws[1] + ws[2] + ws[3]), 1e-12f);
    __nv_bfloat162 p0 = __floats2bfloat162_rn(v.x * inv, v.y * inv);
    __nv_bfloat162 p1 = __floats2bfloat162_rn(v.z * inv, v.w * inv);
    uint2 w;
    w.x = *(uint32_t*)&p0;
    w.y = *(uint32_t*)&p1;
    ((uint2*)(g_fb + row * DIM))[t] = w;
}

// ---------------------------------------------------------------------------
// Kernel 2: symmetric-triangle HMMA bf16 GEMM + vectorized dual scans
// ---------------------------------------------------------------------------
__device__ __forceinline__ void prefetch_chunk(uint32_t s_base, int st, int row0,
                                               int col0, int kb, int tid) {
    const uint32_t stf = s_base + st * STAGE_BYTES;
    #pragma unroll
    for (int i = tid; i < MT * 8; i += 256) {
        int r = i >> 3, sg = i & 7;
        cpa16(stf + (r * PITCHH + sg * 8) * 2, g_fb + (row0 + r) * DIM + kb + sg * 8);
    }
    #pragma unroll
    for (int i = tid; i < NT * 8; i += 256) {
        int r = i >> 3, sg = i & 7;
        cpa16(stf + AB_HALVES * 2 + (r * PITCHH + sg * 8) * 2,
              g_fb + (col0 + r) * DIM + kb + sg * 8);
    }
    CP_COMMIT();
}

__global__ __launch_bounds__(256, 2)
void sim_kernel() {
    extern __shared__ float smem[];
    const uint32_t s_base = smem_u32(smem);
    const int tid  = threadIdx.x;
    const int lane = tid & 31, warp = tid >> 5;

    // decode blockIdx -> (I, J) with I <= J
    const int b = blockIdx.x;
    int J = (int)((sqrtf(8.0f * b + 1.0f) - 1.0f) * 0.5f);
    while ((J + 1) * (J + 2) / 2 <= b) ++J;
    while (J * (J + 1) / 2 > b) --J;
    const int I = b - J * (J + 1) / 2;
    const int row0 = I * MT;
    const int col0 = J * NT;
    const bool DIAG = (I == J);

    int* idxI = (int*)((char*)smem + IDX_OFF);        // strip I indices
    int* idxJ = idxI + 128;                           // strip J indices
    if (tid < 128) {
        idxI[tid] = g_idx[row0 + tid];
        idxJ[tid] = g_idx[col0 + tid];
    }

    const int wm = warp >> 1, wn = warp & 1;
    const int qg = lane >> 2, qt = lane & 3;

    uint32_t aoff[2], boff[4];
    {
        const int l7 = lane & 7, l8 = (lane >> 3) & 1, l16 = (lane >> 4) & 1;
        #pragma unroll
        for (int i = 0; i < 2; i++) {
            int rowA = wm * 32 + i * 16 + l8 * 8 + l7;
            aoff[i] = (uint32_t)((rowA * PITCHH + l16 * 8) * 2);
        }
        #pragma unroll
        for (int jp = 0; jp < 4; jp++) {
            int nB = wn * 64 + jp * 16 + l16 * 8 + l7;
            boff[jp] = (uint32_t)(AB_HALVES * 2 + (nB * PITCHH + l8 * 8) * 2);
        }
    }

    float acc[2][8][4];
    #pragma unroll
    for (int i = 0; i < 2; i++)
        #pragma unroll
        for (int j = 0; j < 8; j++)
            #pragma unroll
            for (int q = 0; q < 4; q++) acc[i][j][q] = 0.f;

    prefetch_chunk(s_base, 0, row0, col0, 0, tid);
    prefetch_chunk(s_base, 1, row0, col0, KC, tid);

    for (int c = 0; c < NCHUNK; c++) {
        const int st = c & 1;
        if (c >= NCHUNK - 2) { CP_WAIT0(); } else { CP_WAIT1(); }
        __syncthreads();
        const uint32_t stb = s_base + st * STAGE_BYTES;
        #pragma unroll
        for (int ks = 0; ks < 4; ks++) {
            const uint32_t ko = ks * 32;
            uint32_t a0[4], a1[4], bb[4][4];
            ldsm_x4(a0, stb + aoff[0] + ko);
            ldsm_x4(a1, stb + aoff[1] + ko);
            #pragma unroll
            for (int jp = 0; jp < 4; jp++) ldsm_x4(bb[jp], stb + boff[jp] + ko);
            #pragma unroll
            for (int jp = 0; jp < 4; jp++) {
                mma16(acc[0][2 * jp],     a0, bb[jp][0], bb[jp][1]);
                mma16(acc[1][2 * jp],     a1, bb[jp][0], bb[jp][1]);
                mma16(acc[0][2 * jp + 1], a0, bb[jp][2], bb[jp][3]);
                mma16(acc[1][2 * jp + 1], a1, bb[jp][2], bb[jp][3]);
            }
        }
        __syncthreads();
        if (c + 2 < NCHUNK)
            prefetch_chunk(s_base, st, row0, col0, (c + 2) * KC, tid);
    }

    // stage C tile (aliases stage buffers; all mma reads complete)
    float* Cs = smem;
    float* Ps = smem + 128 * CPITCH;    // 128 x 9 partial-exchange floats
    #pragma unroll
    for (int i = 0; i < 2; i++) {
        #pragma unroll
        for (int j = 0; j < 8; j++) {
            int r = wm * 32 + i * 16 + qg;
            int cc = wn * 64 + j * 8 + 2 * qt;
            Cs[r * CPITCH + cc]           = acc[i][j][0];
            Cs[r * CPITCH + cc + 1]       = acc[i][j][1];
            Cs[(r + 8) * CPITCH + cc]     = acc[i][j][2];
            Cs[(r + 8) * CPITCH + cc + 1] = acc[i][j][3];
        }
    }
    __syncthreads();

    const int sidx = tid & 127, shalf = tid >> 7;

    // ---- row scan: strip I rows over strip J cols -> slot J (float4 packs) ----
    {
        const int myrow = row0 + sidx;
        const int myidx = idxI[sidx];
        ScanAcc A; A.init();
        const float4* crow4 = (const float4*)(Cs + sidx * CPITCH) + shalf * 16;
        const int4*   idx4  = (const int4*)idxJ + shalf * 16;
        const int cbase0 = col0 + shalf * 64;
        #pragma unroll 4
        for (int p = 0; p < 16; p++) {
            float4 v = crow4[p];
            int4  q = idx4[p];
            float m = fmaxf(fmaxf(v.x, v.y), fmaxf(v.z, v.w));
            int cb = cbase0 + p * 4;
            if (m > A.t4) {
                if (!DIAG || cb + 0 != myrow) A.hard(v.x);
                if (!DIAG || cb + 1 != myrow) A.hard(v.y);
                if (!DIAG || cb + 2 != myrow) A.hard(v.z);
                if (!DIAG || cb + 3 != myrow) A.hard(v.w);
            }
            if ((q.x == myidx) | (q.y == myidx) | (q.z == myidx) | (q.w == myidx)) {
                if (q.x == myidx && (!DIAG || cb + 0 != myrow)) A.pos(v.x);
                if (q.y == myidx && (!DIAG || cb + 1 != myrow)) A.pos(v.y);
                if (q.z == myidx && (!DIAG || cb + 2 != myrow)) A.pos(v.z);
                if (q.w == myidx && (!DIAG || cb + 3 != myrow)) A.pos(v.w);
            }
        }
        if (shalf) {
            float* pp = Ps + sidx * 9;
            pp[0] = A.S; pp[1] = A.P; pp[2] = A.n; pp[3] = A.rm;
            pp[4] = A.t0; pp[5] = A.t1; pp[6] = A.t2; pp[7] = A.t3; pp[8] = A.t4;
        }
        __syncthreads();
        if (!shalf) {
            const float* pp = Ps + sidx * 9;
            A.S += pp[0]; A.P += pp[1]; A.n += pp[2]; A.rm = fmaxf(A.rm, pp[3]);
            A.hard(pp[4]); A.hard(pp[5]); A.hard(pp[6]); A.hard(pp[7]); A.hard(pp[8]);
            float* gp = g_part + ((size_t)myrow * NSLOT + J) * PSTRIDE;
            gp[0] = A.S; gp[1] = A.P; gp[2] = A.n; gp[3] = A.rm;
            gp[4] = A.t0; gp[5] = A.t1; gp[6] = A.t2; gp[7] = A.t3; gp[8] = A.t4;
        }
    }

    if (DIAG) return;   // diagonal: row scan fully covers

    __syncthreads();    // Ps reuse

    // ---- col scan: strip J rows over strip I cols -> slot I ----
    {
        const int myrow = col0 + sidx;
        const int myidx = idxJ[sidx];
        ScanAcc A; A.init();
        const int rbase = shalf * 64;
        #pragma unroll 4
        for (int p = 0; p < 16; p++) {
            int rr = rbase + p * 4;
            float v0 = Cs[(rr + 0) * CPITCH + sidx];
            float v1 = Cs[(rr + 1) * CPITCH + sidx];
            float v2 = Cs[(rr + 2) * CPITCH + sidx];
            float v3 = Cs[(rr + 3) * CPITCH + sidx];
            int4 q = *(const int4*)(idxI + rr);
            float m = fmaxf(fmaxf(v0, v1), fmaxf(v2, v3));
            if (m > A.t4) { A.hard(v0); A.hard(v1); A.hard(v2); A.hard(v3); }
            if ((q.x == myidx) | (q.y == myidx) | (q.z == myidx) | (q.w == myidx)) {
                if (q.x == myidx) A.pos(v0);
                if (q.y == myidx) A.pos(v1);
                if (q.z == myidx) A.pos(v2);
                if (q.w == myidx) A.pos(v3);
            }
        }
        if (shalf) {
            float* pp = Ps + sidx * 9;
            pp[0] = A.S; pp[1] = A.P; pp[2] = A.n; pp[3] = A.rm;
            pp[4] = A.t0; pp[5] = A.t1; pp[6] = A.t2; pp[7] = A.t3; pp[8] = A.t4;
        }
        __syncthreads();
        if (!shalf) {
            const float* pp = Ps + sidx * 9;
            A.S += pp[0]; A.P += pp[1]; A.n += pp[2]; A.rm = fmaxf(A.rm, pp[3]);
            A.hard(pp[4]); A.hard(pp[5]); A.hard(pp[6]); A.hard(pp[7]); A.hard(pp[8]);
            float* gp = g_part + ((size_t)myrow * NSLOT + I) * PSTRIDE;
            gp[0] = A.S; gp[1] = A.P; gp[2] = A.n; gp[3] = A.rm;
            gp[4] = A.t0; gp[5] = A.t1; gp[6] = A.t2; gp[7] = A.t3; gp[8] = A.t4;
        }
    }
}

// ---------------------------------------------------------------------------
// Kernel 3: parallel merge — 8 threads/row, shfl butterfly; global max
// ---------------------------------------------------------------------------
__global__ void merge_kernel() {
    const int tid = threadIdx.x;
    const int lane = tid & 31;
    const int sub = lane & 7;
    const int r = blockIdx.x * 32 + (tid >> 3);

    const float4* base = (const float4*)(g_part + (size_t)r * NSLOT * PSTRIDE);
    float S = 0.f, P = 0.f, n = 0.f, rm = -CUDART_INF_F;
    float t0 = -CUDART_INF_F, t1 = -CUDART_INF_F, t2 = -CUDART_INF_F,
          t3 = -CUDART_INF_F, t4 = -CUDART_INF_F;
    #pragma unroll
    for (int q = 0; q < 8; q++) {
        int s = sub + q * 8;
        float4 a = base[s * 3 + 0];
        float4 c = base[s * 3 + 1];
        float4 d = base[s * 3 + 2];
        S += a.x; P += a.y; n += a.z; rm = fmaxf(rm, a.w);
        top5_ins(c.x, t0, t1, t2, t3, t4);
        top5_ins(c.y, t0, t1, t2, t3, t4);
        top5_ins(c.z, t0, t1, t2, t3, t4);
        top5_ins(c.w, t0, t1, t2, t3, t4);
        top5_ins(d.x, t0, t1, t2, t3, t4);
    }
    #pragma unroll
    for (int o = 1; o < 8; o <<= 1) {
        S += __shfl_xor_sync(0xffffffffu, S, o);
        P += __shfl_xor_sync(0xffffffffu, P, o);
        n += __shfl_xor_sync(0xffffffffu, n, o);
        rm = fmaxf(rm, __shfl_xor_sync(0xffffffffu, rm, o));
        float m0 = __shfl_xor_sync(0xffffffffu, t0, o);
        float m1 = __shfl_xor_sync(0xffffffffu, t1, o);
        float m2 = __shfl_xor_sync(0xffffffffu, t2, o);
        float m3 = __shfl_xor_sync(0xffffffffu, t3, o);
        float m4 = __shfl_xor_sync(0xffffffffu, t4, o);
        top5_ins(m0, t0, t1, t2, t3, t4);
        top5_ins(m1, t0, t1, t2, t3, t4);
        top5_ins(m2, t0, t1, t2, t3, t4);
        top5_ins(m3, t0, t1, t2, t3, t4);
        top5_ins(m4, t0, t1, t2, t3, t4);
    }
    if (sub == 0) {
        g_D1[r] = (n > 0.f) ? __expf(-rm * T_INV) * P : 0.f;
        float H = __expf(t0 * T_INV) + __expf(t1 * T_INV) + __expf(t2 * T_INV) +
                  __expf(t3 * T_INV) + __expf(t4 * T_INV);
        g_H[r] = (n > 0.f) ? H : -1.f;
        g_B[r] = (n > 0.f) ? (S * T_INV) / n : 0.f;
    }

    __shared__ unsigned sm[256];
    sm[tid] = fkey(t0);
    __syncthreads();
    for (int s = 128; s; s >>= 1) {
        if (tid < s) sm[tid] = max(sm[tid], sm[tid + s]);
        __syncthreads();
    }
    if (tid == 0) atomicMax(&g_Gkey, sm[0]);
}

// ---------------------------------------------------------------------------
// Kernel 4: final loss
// ---------------------------------------------------------------------------
__global__ void finalize_kernel(float* __restrict__ out) {
    __shared__ float sh[1024];
    int tid = threadIdx.x;
    float G = funkey(g_Gkey) * T_INV;
    float eG = __expf(-G);
    float sum = 0.f;
    for (int r = tid; r < BATCH; r += 1024) {
        float H = g_H[r];
        if (H >= 0.f)
            sum += __logf(g_D1[r] + eG * H) - g_B[r];
    }
    sh[tid] = sum;
    __syncthreads();
    for (int s = 512; s; s >>= 1) {
        if (tid < s) sh[tid] += sh[tid + s];
        __syncthreads();
    }
    if (tid == 0) out[0] = sh[0] / (float)BATCH;
}

// ---------------------------------------------------------------------------
extern "C" void kernel_launch(void* const* d_in, const int* in_sizes, int n_in,
                              void* d_out, int out_size) {
    const float* x   = (const float*)d_in[0];
    const int*   idx = (const int*)d_in[1];
    float*       out = (float*)d_out;

    cudaFuncSetAttribute(sim_kernel, cudaFuncAttributeMaxDynamicSharedMemorySize,
                         SMEM_BYTES);

    prep_idx_kernel<<<1, 256>>>(idx);
    normalize_kernel<<<BATCH, 128>>>(x);
    sim_kernel<<<NTILE, 256, SMEM_BYTES>>>();
    merge_kernel<<<BATCH / 32, 256>>>();
    finalize_kernel<<<1, 1024>>>(out);
}